// round 12
// baseline (speedup 1.0000x reference)
#include <cuda_runtime.h>
#include <cuda_fp16.h>
#include <cstdint>

// ---------------------------------------------------------------------------
// EdgeConv (mlp_layer=0, aggregate=max), restructured:
//   t      = feat @ theta_w                      [N, 64]
//   base   = t + feat @ phi_w + theta_b + phi_b  [N, 64]   (fp16 scratch)
//   out[v] = base[v] - min_k t[nbr[v,k]]         (per-feature min, fp32 out)
//
// SINGLE persistent kernel (grid = resident capacity):
//   phase 0: convert B to fp16 [n][k] in smem (once per CTA)
//   phase 1: grid-stride mma.sync GEMM tiles (2-pass A hi/lo split)
//   device-wide barrier (monotonic ticket counter; replay-safe, no reset)
//   phase 2: grid-stride gather-min (2 nodes/warp), writes fp32 out
// Removes 2 kernel-launch overheads (~4us each) + GEMM wave tail.
// ---------------------------------------------------------------------------

#define F_DIM 64
#define N_MAX 120000

__device__ __half g_t16[(size_t)N_MAX * F_DIM];     // fp16 t
__device__ __half g_base16[(size_t)N_MAX * F_DIM];  // fp16 base
__device__ unsigned long long g_ctr = 0;            // barrier ticket counter

// ============================= PTX helpers =================================
__device__ __forceinline__ uint32_t smem_u32(const void* p) {
    uint32_t a;
    asm("{ .reg .u64 tmp; cvta.to.shared.u64 tmp, %1; cvt.u32.u64 %0, tmp; }"
        : "=r"(a) : "l"(p));
    return a;
}

__device__ __forceinline__ void ldsm_x4(uint32_t* r, uint32_t addr) {
    asm volatile("ldmatrix.sync.aligned.m8n8.x4.shared.b16 {%0,%1,%2,%3}, [%4];"
                 : "=r"(r[0]), "=r"(r[1]), "=r"(r[2]), "=r"(r[3]) : "r"(addr));
}

__device__ __forceinline__ void mma16816(float* c, const uint32_t* a,
                                         const uint32_t* b) {
    asm volatile(
        "mma.sync.aligned.m16n8k16.row.col.f32.f16.f16.f32 "
        "{%0,%1,%2,%3}, {%4,%5,%6,%7}, {%8,%9}, {%0,%1,%2,%3};"
        : "+f"(c[0]), "+f"(c[1]), "+f"(c[2]), "+f"(c[3])
        : "r"(a[0]), "r"(a[1]), "r"(a[2]), "r"(a[3]), "r"(b[0]), "r"(b[1]));
}

__device__ __forceinline__ uint32_t pack_hilo(float x, float y,
                                              uint32_t& lo_out) {
    __half hx = __float2half_rn(x);
    __half hy = __float2half_rn(y);
    __half lx = __float2half_rn(x - __half2float(hx));
    __half ly = __float2half_rn(y - __half2float(hy));
    lo_out = (uint32_t)__half_as_ushort(lx) |
             ((uint32_t)__half_as_ushort(ly) << 16);
    return (uint32_t)__half_as_ushort(hx) |
           ((uint32_t)__half_as_ushort(hy) << 16);
}

// SMEM layout (dynamic, bytes). 144-B rows: ldmatrix conflict-free.
#define SM_AH 0
#define SM_AL 9216
#define SM_BH 18432
#define SM_BYTES 36864     // < 48KB default limit -> no attribute needed

// ============================ fused kernel =================================
__global__ __launch_bounds__(256, 4)
void fused_kernel(const float* __restrict__ feat,
                  const void*  __restrict__ nbr_raw,
                  const float* __restrict__ theta_w,
                  const float* __restrict__ theta_b,
                  const float* __restrict__ phi_w,
                  const float* __restrict__ phi_b,
                  float* __restrict__ out,
                  int n, int K, int ntiles)
{
    extern __shared__ char sm[];
    const uint32_t sbase = smem_u32(sm);
    const int tid  = threadIdx.x;
    const int wid  = tid >> 5;
    const int lane = tid & 31;

    // ======== phase 0: B -> fp16 smem [nrow][k]; nrow<64 theta, >=64 phi ===
#pragma unroll
    for (int p = 0; p < 32; p++) {
        int idx = tid + p * 256;       // 0..8191
        int c   = idx & 127;           // coalesced read dim
        int k   = idx >> 7;            // 0..63
        const float* w = (c < 64) ? theta_w : phi_w;
        float v = w[k * F_DIM + (c & 63)];
        *(__half*)(sm + SM_BH + c * 144 + k * 2) = __float2half_rn(v);
    }

    const int wm = (wid & 1) * 32;
    const int wn = (wid >> 1) * 16;
    const int li = lane & 7;
    const int lg = lane >> 3;

    // ======== phase 1: grid-stride GEMM tiles ==============================
    for (int tile = blockIdx.x; tile < ntiles; tile += gridDim.x) {
        __syncthreads();               // smem A reuse guard (and B ready)
        const int rb = tile * 64;

        // ---- stage A: feat rows -> fp16 hi/lo (coalesced float4) ----------
#pragma unroll
        for (int p = 0; p < 4; p++) {
            int idx = tid + p * 256;   // 0..1023
            int c4  = idx & 15;
            int row = idx >> 4;
            float4 f = make_float4(0.f, 0.f, 0.f, 0.f);
            int gr = rb + row;
            if (gr < n) f = *(const float4*)&feat[(size_t)gr * F_DIM + c4 * 4];
            uint32_t l0, l1;
            uint32_t h0 = pack_hilo(f.x, f.y, l0);
            uint32_t h1 = pack_hilo(f.z, f.w, l1);
            uint32_t off = row * 144 + c4 * 8;
            *(uint2*)(sm + SM_AH + off) = make_uint2(h0, h1);
            *(uint2*)(sm + SM_AL + off) = make_uint2(l0, l1);
        }
        __syncthreads();

        float accT[2][2][4], accP[2][2][4];
#pragma unroll
        for (int mt = 0; mt < 2; mt++)
#pragma unroll
            for (int nt = 0; nt < 2; nt++)
#pragma unroll
                for (int j = 0; j < 4; j++) {
                    accT[mt][nt][j] = 0.f;
                    accP[mt][nt][j] = 0.f;
                }

#pragma unroll
        for (int ks = 0; ks < 4; ks++) {
            const int k0 = ks * 16;
            uint32_t bT[2][2], bP[2][2];
            {
                int row = wn + li + (lg >> 1) * 8;
                int col = k0 + (lg & 1) * 8;
                uint32_t r[4];
                ldsm_x4(r, sbase + SM_BH + row * 144 + col * 2);
                bT[0][0] = r[0]; bT[0][1] = r[1];
                bT[1][0] = r[2]; bT[1][1] = r[3];
                ldsm_x4(r, sbase + SM_BH + (64 + row) * 144 + col * 2);
                bP[0][0] = r[0]; bP[0][1] = r[1];
                bP[1][0] = r[2]; bP[1][1] = r[3];
            }
#pragma unroll
            for (int p = 0; p < 2; p++) {
                const uint32_t aoff = p ? SM_AL : SM_AH;
                uint32_t a[2][4];
#pragma unroll
                for (int mt = 0; mt < 2; mt++) {
                    int row = wm + mt * 16 + li + (lg & 1) * 8;
                    int col = k0 + (lg >> 1) * 8;
                    ldsm_x4(a[mt], sbase + aoff + row * 144 + col * 2);
                }
#pragma unroll
                for (int mt = 0; mt < 2; mt++)
#pragma unroll
                    for (int nt = 0; nt < 2; nt++) {
                        mma16816(accT[mt][nt], a[mt], bT[nt]);
                        mma16816(accP[mt][nt], a[mt], bP[nt]);
                    }
            }
        }

        // ---- epilogue: t (fp16) and base (fp16) ---------------------------
#pragma unroll
        for (int mt = 0; mt < 2; mt++) {
            int r0 = rb + wm + mt * 16 + (lane >> 2);
#pragma unroll
            for (int nt = 0; nt < 2; nt++) {
                int col = wn + nt * 8 + 2 * (lane & 3);
                float b0 = theta_b[col]     + phi_b[col];
                float b1 = theta_b[col + 1] + phi_b[col + 1];
                if (r0 < n) {
                    size_t o = (size_t)r0 * F_DIM + col;
                    float t0 = accT[mt][nt][0], t1 = accT[mt][nt][1];
                    *(__half2*)&g_t16[o] = __floats2half2_rn(t0, t1);
                    *(__half2*)&g_base16[o] =
                        __floats2half2_rn(t0 + accP[mt][nt][0] + b0,
                                          t1 + accP[mt][nt][1] + b1);
                }
                int r1 = r0 + 8;
                if (r1 < n) {
                    size_t o = (size_t)r1 * F_DIM + col;
                    float t2 = accT[mt][nt][2], t3 = accT[mt][nt][3];
                    *(__half2*)&g_t16[o] = __floats2half2_rn(t2, t3);
                    *(__half2*)&g_base16[o] =
                        __floats2half2_rn(t2 + accP[mt][nt][2] + b0,
                                          t3 + accP[mt][nt][3] + b1);
                }
            }
        }
    }

    // ======== device-wide barrier (replay-safe monotonic ticket) ===========
    __threadfence();                   // release all t16/base16 stores
    __syncthreads();                   // whole CTA done before arriving
    if (tid == 0) {
        unsigned long long ticket = atomicAdd(&g_ctr, 1ULL);
        unsigned long long gd     = (unsigned long long)gridDim.x;
        unsigned long long target = (ticket / gd + 1ULL) * gd;
        while (*(volatile unsigned long long*)&g_ctr < target)
            __nanosleep(64);
        __threadfence();               // acquire
    }
    __syncthreads();

    // ======== phase 2: gather-min, 2 nodes per warp ========================
    // dtype detect (uniform): int64 indices < 2^31 have zero odd words
    unsigned int probe = ((const unsigned int*)nbr_raw)[lane];
    bool oddzero = ((lane & 1) == 0) || (probe == 0u);
    const bool is64 = (__ballot_sync(0xFFFFFFFFu, oddzero) == 0xFFFFFFFFu);

    const int half = lane >> 4;
    const int hl   = lane & 15;
    const int P    = (n + 1) >> 1;             // node pairs
    const int gwarp  = blockIdx.x * 8 + wid;
    const int nwarps = gridDim.x * 8;
    const uint2* tp = (const uint2*)g_t16;     // 16 uint2 per row

    for (int pair = gwarp; pair < P; pair += nwarps) {
        int node = pair * 2 + half;
        if (node >= n) node = n - 1;           // odd-tail duplicate (benign)

        __half2 m0 = __float2half2_rn(65504.f);
        __half2 m1 = m0;

        if (K == 16) {
            int myidx = is64
                ? (int)((const long long*)nbr_raw)[(size_t)node * 16 + hl]
                : ((const int*)nbr_raw)[(size_t)node * 16 + hl];
#pragma unroll
            for (int j = 0; j < 16; j++) {
                int uj = __shfl_sync(0xFFFFFFFFu, myidx, j, 16);
                uint2 v = __ldg(&tp[uj * 16 + hl]);
                m0 = __hmin2(m0, *(__half2*)&v.x);
                m1 = __hmin2(m1, *(__half2*)&v.y);
            }
        } else {
            for (int j = 0; j < K; j++) {
                int uj = is64
                    ? (int)((const long long*)nbr_raw)[(size_t)node * K + j]
                    : ((const int*)nbr_raw)[(size_t)node * K + j];
                uint2 v = __ldg(&tp[uj * 16 + hl]);
                m0 = __hmin2(m0, *(__half2*)&v.x);
                m1 = __hmin2(m1, *(__half2*)&v.y);
            }
        }

        size_t o = (size_t)node * 16 + hl;
        uint2 bb = *((const uint2*)g_base16 + o);
        float2 B0 = __half22float2(*(__half2*)&bb.x);
        float2 B1 = __half22float2(*(__half2*)&bb.y);
        float2 f0 = __half22float2(m0);
        float2 f1 = __half22float2(m1);
        ((float4*)out)[o] = make_float4(B0.x - f0.x, B0.y - f0.y,
                                        B1.x - f1.x, B1.y - f1.y);
    }
}

// ============================== launch =====================================
extern "C" void kernel_launch(void* const* d_in, const int* in_sizes, int n_in,
                              void* d_out, int out_size)
{
    const float* feat    = (const float*)d_in[0];
    const void*  nbr     = d_in[1];
    const float* theta_w = (const float*)d_in[2];
    const float* theta_b = (const float*)d_in[3];
    const float* phi_w   = (const float*)d_in[4];
    const float* phi_b   = (const float*)d_in[5];
    float* out = (float*)d_out;

    const int n = in_sizes[0] / F_DIM;     // number of nodes
    const int K = in_sizes[1] / n;         // neighbors per node (=16)
    const int ntiles = (n + 63) / 64;

    // Grid = exactly the resident capacity (spin barrier requires residency).
    int dev = 0;
    cudaGetDevice(&dev);
    int sms = 0;
    cudaDeviceGetAttribute(&sms, cudaDevAttrMultiProcessorCount, dev);
    int maxb = 0;
    cudaOccupancyMaxActiveBlocksPerMultiprocessor(&maxb, fused_kernel, 256,
                                                  SM_BYTES);
    if (maxb < 1) maxb = 1;
    if (maxb > 4) maxb = 4;
    int grid = sms * maxb;

    fused_kernel<<<grid, 256, SM_BYTES>>>(feat, nbr, theta_w, theta_b,
                                          phi_w, phi_b, out, n, K, ntiles);
}

// round 13
// speedup vs baseline: 1.1407x; 1.1407x over previous
#include <cuda_runtime.h>
#include <cuda_fp16.h>
#include <cstdint>

// ---------------------------------------------------------------------------
// EdgeConv (mlp_layer=0, aggregate=max), restructured:
//   t      = feat @ theta_w                      [N, 64]
//   base   = t + feat @ phi_w + theta_b + phi_b  [N, 64]   (fp16 scratch)
//   out[v] = base[v] - min_k t[nbr[v,k]]         (per-feature min, fp32 out)
//
// Kernel 1: PERSISTENT mma.sync GEMM (grid-stride tiles). B converted to fp16
//           smem once per resident CTA (no prep kernel, no wave tail).
// Kernel 2: standalone gather-min (2 nodes/warp, full occupancy - the fused
//           variant proved the gather needs ~53 warps/SM, not 32).
// ---------------------------------------------------------------------------

#define F_DIM 64
#define N_MAX 120000

__device__ __half g_t16[(size_t)N_MAX * F_DIM];     // fp16 t
__device__ __half g_base16[(size_t)N_MAX * F_DIM];  // fp16 base

// ============================= PTX helpers =================================
__device__ __forceinline__ uint32_t smem_u32(const void* p) {
    uint32_t a;
    asm("{ .reg .u64 tmp; cvta.to.shared.u64 tmp, %1; cvt.u32.u64 %0, tmp; }"
        : "=r"(a) : "l"(p));
    return a;
}

__device__ __forceinline__ void ldsm_x4(uint32_t* r, uint32_t addr) {
    asm volatile("ldmatrix.sync.aligned.m8n8.x4.shared.b16 {%0,%1,%2,%3}, [%4];"
                 : "=r"(r[0]), "=r"(r[1]), "=r"(r[2]), "=r"(r[3]) : "r"(addr));
}

__device__ __forceinline__ void mma16816(float* c, const uint32_t* a,
                                         const uint32_t* b) {
    asm volatile(
        "mma.sync.aligned.m16n8k16.row.col.f32.f16.f16.f32 "
        "{%0,%1,%2,%3}, {%4,%5,%6,%7}, {%8,%9}, {%0,%1,%2,%3};"
        : "+f"(c[0]), "+f"(c[1]), "+f"(c[2]), "+f"(c[3])
        : "r"(a[0]), "r"(a[1]), "r"(a[2]), "r"(a[3]), "r"(b[0]), "r"(b[1]));
}

__device__ __forceinline__ uint32_t pack_hilo(float x, float y,
                                              uint32_t& lo_out) {
    __half hx = __float2half_rn(x);
    __half hy = __float2half_rn(y);
    __half lx = __float2half_rn(x - __half2float(hx));
    __half ly = __float2half_rn(y - __half2float(hy));
    lo_out = (uint32_t)__half_as_ushort(lx) |
             ((uint32_t)__half_as_ushort(ly) << 16);
    return (uint32_t)__half_as_ushort(hx) |
           ((uint32_t)__half_as_ushort(hy) << 16);
}

// SMEM layout (dynamic, bytes). 144-B rows: ldmatrix conflict-free.
#define SM_AH 0
#define SM_AL 9216
#define SM_BH 18432
#define SM_BYTES 36864     // < 48KB default limit

// ===================== kernel 1: persistent GEMM ===========================
// CTA: 64-row tiles, grid-stride. 8 warps: wm=(wid&1)*32, wn=(wid>>1)*16.
// Warp owns theta cols wn..wn+15 and phi cols 64+wn..+15 -> t and base
// combine in registers. 2-pass A hi/lo split vs single-fp16 B.
__global__ __launch_bounds__(256, 4)
void gemm_mma_kernel(const float* __restrict__ feat,
                     const float* __restrict__ theta_w,
                     const float* __restrict__ theta_b,
                     const float* __restrict__ phi_w,
                     const float* __restrict__ phi_b,
                     int n, int ntiles)
{
    extern __shared__ char sm[];
    const uint32_t sbase = smem_u32(sm);
    const int tid  = threadIdx.x;
    const int wid  = tid >> 5;
    const int lane = tid & 31;

    // ---- once per CTA: B -> fp16 smem [nrow][k]; nrow<64 theta, >=64 phi --
#pragma unroll
    for (int p = 0; p < 32; p++) {
        int idx = tid + p * 256;       // 0..8191
        int c   = idx & 127;           // coalesced read dim
        int k   = idx >> 7;            // 0..63
        const float* w = (c < 64) ? theta_w : phi_w;
        float v = w[k * F_DIM + (c & 63)];
        *(__half*)(sm + SM_BH + c * 144 + k * 2) = __float2half_rn(v);
    }

    const int wm = (wid & 1) * 32;
    const int wn = (wid >> 1) * 16;
    const int li = lane & 7;
    const int lg = lane >> 3;

    for (int tile = blockIdx.x; tile < ntiles; tile += gridDim.x) {
        __syncthreads();               // A-reuse guard (and B ready, 1st iter)
        const int rb = tile * 64;

        // ---- stage A: feat rows -> fp16 hi/lo (coalesced float4) ----------
#pragma unroll
        for (int p = 0; p < 4; p++) {
            int idx = tid + p * 256;   // 0..1023
            int c4  = idx & 15;
            int row = idx >> 4;
            float4 f = make_float4(0.f, 0.f, 0.f, 0.f);
            int gr = rb + row;
            if (gr < n) f = *(const float4*)&feat[(size_t)gr * F_DIM + c4 * 4];
            uint32_t l0, l1;
            uint32_t h0 = pack_hilo(f.x, f.y, l0);
            uint32_t h1 = pack_hilo(f.z, f.w, l1);
            uint32_t off = row * 144 + c4 * 8;
            *(uint2*)(sm + SM_AH + off) = make_uint2(h0, h1);
            *(uint2*)(sm + SM_AL + off) = make_uint2(l0, l1);
        }
        __syncthreads();

        float accT[2][2][4], accP[2][2][4];
#pragma unroll
        for (int mt = 0; mt < 2; mt++)
#pragma unroll
            for (int nt = 0; nt < 2; nt++)
#pragma unroll
                for (int j = 0; j < 4; j++) {
                    accT[mt][nt][j] = 0.f;
                    accP[mt][nt][j] = 0.f;
                }

#pragma unroll
        for (int ks = 0; ks < 4; ks++) {
            const int k0 = ks * 16;
            uint32_t bT[2][2], bP[2][2];
            {
                int row = wn + li + (lg >> 1) * 8;
                int col = k0 + (lg & 1) * 8;
                uint32_t r[4];
                ldsm_x4(r, sbase + SM_BH + row * 144 + col * 2);
                bT[0][0] = r[0]; bT[0][1] = r[1];
                bT[1][0] = r[2]; bT[1][1] = r[3];
                ldsm_x4(r, sbase + SM_BH + (64 + row) * 144 + col * 2);
                bP[0][0] = r[0]; bP[0][1] = r[1];
                bP[1][0] = r[2]; bP[1][1] = r[3];
            }
#pragma unroll
            for (int p = 0; p < 2; p++) {
                const uint32_t aoff = p ? SM_AL : SM_AH;
                uint32_t a[2][4];
#pragma unroll
                for (int mt = 0; mt < 2; mt++) {
                    int row = wm + mt * 16 + li + (lg & 1) * 8;
                    int col = k0 + (lg >> 1) * 8;
                    ldsm_x4(a[mt], sbase + aoff + row * 144 + col * 2);
                }
#pragma unroll
                for (int mt = 0; mt < 2; mt++)
#pragma unroll
                    for (int nt = 0; nt < 2; nt++) {
                        mma16816(accT[mt][nt], a[mt], bT[nt]);
                        mma16816(accP[mt][nt], a[mt], bP[nt]);
                    }
            }
        }

        // ---- epilogue: t (fp16) and base (fp16) ---------------------------
#pragma unroll
        for (int mt = 0; mt < 2; mt++) {
            int r0 = rb + wm + mt * 16 + (lane >> 2);
#pragma unroll
            for (int nt = 0; nt < 2; nt++) {
                int col = wn + nt * 8 + 2 * (lane & 3);
                float b0 = theta_b[col]     + phi_b[col];
                float b1 = theta_b[col + 1] + phi_b[col + 1];
                if (r0 < n) {
                    size_t o = (size_t)r0 * F_DIM + col;
                    float t0 = accT[mt][nt][0], t1 = accT[mt][nt][1];
                    *(__half2*)&g_t16[o] = __floats2half2_rn(t0, t1);
                    *(__half2*)&g_base16[o] =
                        __floats2half2_rn(t0 + accP[mt][nt][0] + b0,
                                          t1 + accP[mt][nt][1] + b1);
                }
                int r1 = r0 + 8;
                if (r1 < n) {
                    size_t o = (size_t)r1 * F_DIM + col;
                    float t2 = accT[mt][nt][2], t3 = accT[mt][nt][3];
                    *(__half2*)&g_t16[o] = __floats2half2_rn(t2, t3);
                    *(__half2*)&g_base16[o] =
                        __floats2half2_rn(t2 + accP[mt][nt][2] + b0,
                                          t3 + accP[mt][nt][3] + b1);
                }
            }
        }
    }
}

// ===================== kernel 2: gather-min ================================
// TWO nodes per warp: lanes 0-15 -> node 2w, lanes 16-31 -> node 2w+1.
// Lane hl owns uint2 chunk hl of the 128-B row. Indices coalesced + shfl.
// Sole writer of out (full coverage of the poisoned buffer).
__global__ __launch_bounds__(256)
void gather_min_kernel(const void* __restrict__ nbr_raw,
                       float* __restrict__ out,
                       int n, int K)
{
    const int lane = threadIdx.x & 31;

    unsigned int probe = ((const unsigned int*)nbr_raw)[lane];
    bool oddzero = ((lane & 1) == 0) || (probe == 0u);
    const bool is64 = (__ballot_sync(0xFFFFFFFFu, oddzero) == 0xFFFFFFFFu);

    long long wpair = (blockIdx.x * (long long)blockDim.x + threadIdx.x) >> 5;
    const int half = lane >> 4;
    const int hl   = lane & 15;
    int node = (int)(wpair * 2) + half;
    if ((int)(wpair * 2) >= n) return;
    if (node >= n) node = n - 1;     // odd-tail duplicate (benign)

    int myidx;
    if (K == 16) {
        myidx = is64 ? (int)((const long long*)nbr_raw)[(size_t)node * 16 + hl]
                     : ((const int*)nbr_raw)[(size_t)node * 16 + hl];
    } else {
        myidx = 0;
    }

    const uint2* tp = (const uint2*)g_t16;   // 16 uint2 per row
    __half2 m0 = __float2half2_rn(65504.f);
    __half2 m1 = m0;

    if (K == 16) {
#pragma unroll
        for (int j = 0; j < 16; j++) {
            int uj = __shfl_sync(0xFFFFFFFFu, myidx, j, 16);
            uint2 v = __ldg(&tp[uj * 16 + hl]);
            m0 = __hmin2(m0, *(__half2*)&v.x);
            m1 = __hmin2(m1, *(__half2*)&v.y);
        }
    } else {
        for (int j = 0; j < K; j++) {
            int uj = is64 ? (int)((const long long*)nbr_raw)[(size_t)node * K + j]
                          : ((const int*)nbr_raw)[(size_t)node * K + j];
            uint2 v = __ldg(&tp[uj * 16 + hl]);
            m0 = __hmin2(m0, *(__half2*)&v.x);
            m1 = __hmin2(m1, *(__half2*)&v.y);
        }
    }

    size_t o = (size_t)node * 16 + hl;
    uint2 bb = *((const uint2*)g_base16 + o);
    float2 B0 = __half22float2(*(__half2*)&bb.x);
    float2 B1 = __half22float2(*(__half2*)&bb.y);
    float2 f0 = __half22float2(m0);
    float2 f1 = __half22float2(m1);
    ((float4*)out)[o] = make_float4(B0.x - f0.x, B0.y - f0.y,
                                    B1.x - f1.x, B1.y - f1.y);
}

// ============================== launch =====================================
extern "C" void kernel_launch(void* const* d_in, const int* in_sizes, int n_in,
                              void* d_out, int out_size)
{
    const float* feat    = (const float*)d_in[0];
    const void*  nbr     = d_in[1];
    const float* theta_w = (const float*)d_in[2];
    const float* theta_b = (const float*)d_in[3];
    const float* phi_w   = (const float*)d_in[4];
    const float* phi_b   = (const float*)d_in[5];
    float* out = (float*)d_out;

    const int n = in_sizes[0] / F_DIM;     // number of nodes
    const int K = in_sizes[1] / n;         // neighbors per node (=16)
    const int ntiles = (n + 63) / 64;

    int dev = 0;
    cudaGetDevice(&dev);
    int sms = 0;
    cudaDeviceGetAttribute(&sms, cudaDevAttrMultiProcessorCount, dev);
    int grid = sms * 4;
    if (grid > ntiles) grid = ntiles;

    gemm_mma_kernel<<<grid, 256, SM_BYTES>>>(feat, theta_w, theta_b,
                                             phi_w, phi_b, n, ntiles);

    long long pairs = ((long long)n + 1) / 2;        // 2 nodes per warp
    long long total_threads = pairs * 32;
    int g2 = (int)((total_threads + 255) / 256);
    gather_min_kernel<<<g2, 256>>>(nbr, out, n, K);
}

// round 14
// speedup vs baseline: 1.1933x; 1.0461x over previous
#include <cuda_runtime.h>
#include <cuda_fp16.h>
#include <cstdint>

// ---------------------------------------------------------------------------
// EdgeConv (mlp_layer=0, aggregate=max), restructured:
//   t      = feat @ theta_w                      [N, 64]
//   base   = t + feat @ phi_w + theta_b + phi_b  [N, 64]   (fp16 scratch)
//   out[v] = base[v] - min_k t[nbr[v,k]]         (per-feature min, fp32 out)
//
// Kernel 1: PERSISTENT mma.sync GEMM, SINGLE fp16 pass (A and B both fp16;
//           measured error stack leaves 3.4x margin under the 1e-3 gate).
//           B converted to fp16 smem once per resident CTA.
// Kernel 2: standalone gather-min (2 nodes/warp, full occupancy), at its
//           compulsory L2-traffic floor (~24us measured).
// ---------------------------------------------------------------------------

#define F_DIM 64
#define N_MAX 120000

__device__ __half g_t16[(size_t)N_MAX * F_DIM];     // fp16 t
__device__ __half g_base16[(size_t)N_MAX * F_DIM];  // fp16 base

// ============================= PTX helpers =================================
__device__ __forceinline__ uint32_t smem_u32(const void* p) {
    uint32_t a;
    asm("{ .reg .u64 tmp; cvta.to.shared.u64 tmp, %1; cvt.u32.u64 %0, tmp; }"
        : "=r"(a) : "l"(p));
    return a;
}

__device__ __forceinline__ void ldsm_x4(uint32_t* r, uint32_t addr) {
    asm volatile("ldmatrix.sync.aligned.m8n8.x4.shared.b16 {%0,%1,%2,%3}, [%4];"
                 : "=r"(r[0]), "=r"(r[1]), "=r"(r[2]), "=r"(r[3]) : "r"(addr));
}

__device__ __forceinline__ void mma16816(float* c, const uint32_t* a,
                                         const uint32_t* b) {
    asm volatile(
        "mma.sync.aligned.m16n8k16.row.col.f32.f16.f16.f32 "
        "{%0,%1,%2,%3}, {%4,%5,%6,%7}, {%8,%9}, {%0,%1,%2,%3};"
        : "+f"(c[0]), "+f"(c[1]), "+f"(c[2]), "+f"(c[3])
        : "r"(a[0]), "r"(a[1]), "r"(a[2]), "r"(a[3]), "r"(b[0]), "r"(b[1]));
}

// SMEM layout (dynamic, bytes). 144-B rows: ldmatrix conflict-free.
#define SM_AH 0
#define SM_BH 9216
#define SM_BYTES 27648     // < 48KB default limit

// ===================== kernel 1: persistent GEMM ===========================
// CTA: 64-row tiles, grid-stride. 8 warps: wm=(wid&1)*32, wn=(wid>>1)*16.
// Warp owns theta cols wn..wn+15 and phi cols 64+wn..+15 -> t and base
// combine in registers. Single fp16 pass.
__global__ __launch_bounds__(256, 4)
void gemm_mma_kernel(const float* __restrict__ feat,
                     const float* __restrict__ theta_w,
                     const float* __restrict__ theta_b,
                     const float* __restrict__ phi_w,
                     const float* __restrict__ phi_b,
                     int n, int ntiles)
{
    extern __shared__ char sm[];
    const uint32_t sbase = smem_u32(sm);
    const int tid  = threadIdx.x;
    const int wid  = tid >> 5;
    const int lane = tid & 31;

    // ---- once per CTA: B -> fp16 smem [nrow][k]; nrow<64 theta, >=64 phi --
#pragma unroll
    for (int p = 0; p < 32; p++) {
        int idx = tid + p * 256;       // 0..8191
        int c   = idx & 127;           // coalesced read dim
        int k   = idx >> 7;            // 0..63
        const float* w = (c < 64) ? theta_w : phi_w;
        float v = w[k * F_DIM + (c & 63)];
        *(__half*)(sm + SM_BH + c * 144 + k * 2) = __float2half_rn(v);
    }

    const int wm = (wid & 1) * 32;
    const int wn = (wid >> 1) * 16;
    const int li = lane & 7;
    const int lg = lane >> 3;

    for (int tile = blockIdx.x; tile < ntiles; tile += gridDim.x) {
        __syncthreads();               // A-reuse guard (and B ready, 1st iter)
        const int rb = tile * 64;

        // ---- stage A: feat rows -> fp16 (coalesced float4) ----------------
#pragma unroll
        for (int p = 0; p < 4; p++) {
            int idx = tid + p * 256;   // 0..1023
            int c4  = idx & 15;
            int row = idx >> 4;
            float4 f = make_float4(0.f, 0.f, 0.f, 0.f);
            int gr = rb + row;
            if (gr < n) f = *(const float4*)&feat[(size_t)gr * F_DIM + c4 * 4];
            __half2 h01 = __floats2half2_rn(f.x, f.y);
            __half2 h23 = __floats2half2_rn(f.z, f.w);
            *(uint2*)(sm + SM_AH + row * 144 + c4 * 8) =
                make_uint2(*(uint32_t*)&h01, *(uint32_t*)&h23);
        }
        __syncthreads();

        float accT[2][2][4], accP[2][2][4];
#pragma unroll
        for (int mt = 0; mt < 2; mt++)
#pragma unroll
            for (int nt = 0; nt < 2; nt++)
#pragma unroll
                for (int j = 0; j < 4; j++) {
                    accT[mt][nt][j] = 0.f;
                    accP[mt][nt][j] = 0.f;
                }

#pragma unroll
        for (int ks = 0; ks < 4; ks++) {
            const int k0 = ks * 16;
            uint32_t bT[2][2], bP[2][2];
            {
                int row = wn + li + (lg >> 1) * 8;
                int col = k0 + (lg & 1) * 8;
                uint32_t r[4];
                ldsm_x4(r, sbase + SM_BH + row * 144 + col * 2);
                bT[0][0] = r[0]; bT[0][1] = r[1];
                bT[1][0] = r[2]; bT[1][1] = r[3];
                ldsm_x4(r, sbase + SM_BH + (64 + row) * 144 + col * 2);
                bP[0][0] = r[0]; bP[0][1] = r[1];
                bP[1][0] = r[2]; bP[1][1] = r[3];
            }
            uint32_t a[2][4];
#pragma unroll
            for (int mt = 0; mt < 2; mt++) {
                int row = wm + mt * 16 + li + (lg & 1) * 8;
                int col = k0 + (lg >> 1) * 8;
                ldsm_x4(a[mt], sbase + SM_AH + row * 144 + col * 2);
            }
#pragma unroll
            for (int mt = 0; mt < 2; mt++)
#pragma unroll
                for (int nt = 0; nt < 2; nt++) {
                    mma16816(accT[mt][nt], a[mt], bT[nt]);
                    mma16816(accP[mt][nt], a[mt], bP[nt]);
                }
        }

        // ---- epilogue: t (fp16) and base (fp16) ---------------------------
#pragma unroll
        for (int mt = 0; mt < 2; mt++) {
            int r0 = rb + wm + mt * 16 + (lane >> 2);
#pragma unroll
            for (int nt = 0; nt < 2; nt++) {
                int col = wn + nt * 8 + 2 * (lane & 3);
                float b0 = theta_b[col]     + phi_b[col];
                float b1 = theta_b[col + 1] + phi_b[col + 1];
                if (r0 < n) {
                    size_t o = (size_t)r0 * F_DIM + col;
                    float t0 = accT[mt][nt][0], t1 = accT[mt][nt][1];
                    *(__half2*)&g_t16[o] = __floats2half2_rn(t0, t1);
                    *(__half2*)&g_base16[o] =
                        __floats2half2_rn(t0 + accP[mt][nt][0] + b0,
                                          t1 + accP[mt][nt][1] + b1);
                }
                int r1 = r0 + 8;
                if (r1 < n) {
                    size_t o = (size_t)r1 * F_DIM + col;
                    float t2 = accT[mt][nt][2], t3 = accT[mt][nt][3];
                    *(__half2*)&g_t16[o] = __floats2half2_rn(t2, t3);
                    *(__half2*)&g_base16[o] =
                        __floats2half2_rn(t2 + accP[mt][nt][2] + b0,
                                          t3 + accP[mt][nt][3] + b1);
                }
            }
        }
    }
}

// ===================== kernel 2: gather-min ================================
// TWO nodes per warp: lanes 0-15 -> node 2w, lanes 16-31 -> node 2w+1.
// Lane hl owns uint2 chunk hl of the 128-B row. Indices coalesced + shfl.
// Sole writer of out (full coverage of the poisoned buffer).
__global__ __launch_bounds__(256)
void gather_min_kernel(const void* __restrict__ nbr_raw,
                       float* __restrict__ out,
                       int n, int K)
{
    const int lane = threadIdx.x & 31;

    unsigned int probe = ((const unsigned int*)nbr_raw)[lane];
    bool oddzero = ((lane & 1) == 0) || (probe == 0u);
    const bool is64 = (__ballot_sync(0xFFFFFFFFu, oddzero) == 0xFFFFFFFFu);

    long long wpair = (blockIdx.x * (long long)blockDim.x + threadIdx.x) >> 5;
    const int half = lane >> 4;
    const int hl   = lane & 15;
    int node = (int)(wpair * 2) + half;
    if ((int)(wpair * 2) >= n) return;
    if (node >= n) node = n - 1;     // odd-tail duplicate (benign)

    int myidx;
    if (K == 16) {
        myidx = is64 ? (int)((const long long*)nbr_raw)[(size_t)node * 16 + hl]
                     : ((const int*)nbr_raw)[(size_t)node * 16 + hl];
    } else {
        myidx = 0;
    }

    const uint2* tp = (const uint2*)g_t16;   // 16 uint2 per row
    __half2 m0 = __float2half2_rn(65504.f);
    __half2 m1 = m0;

    if (K == 16) {
#pragma unroll
        for (int j = 0; j < 16; j++) {
            int uj = __shfl_sync(0xFFFFFFFFu, myidx, j, 16);
            uint2 v = __ldg(&tp[uj * 16 + hl]);
            m0 = __hmin2(m0, *(__half2*)&v.x);
            m1 = __hmin2(m1, *(__half2*)&v.y);
        }
    } else {
        for (int j = 0; j < K; j++) {
            int uj = is64 ? (int)((const long long*)nbr_raw)[(size_t)node * K + j]
                          : ((const int*)nbr_raw)[(size_t)node * K + j];
            uint2 v = __ldg(&tp[uj * 16 + hl]);
            m0 = __hmin2(m0, *(__half2*)&v.x);
            m1 = __hmin2(m1, *(__half2*)&v.y);
        }
    }

    size_t o = (size_t)node * 16 + hl;
    uint2 bb = *((const uint2*)g_base16 + o);
    float2 B0 = __half22float2(*(__half2*)&bb.x);
    float2 B1 = __half22float2(*(__half2*)&bb.y);
    float2 f0 = __half22float2(m0);
    float2 f1 = __half22float2(m1);
    ((float4*)out)[o] = make_float4(B0.x - f0.x, B0.y - f0.y,
                                    B1.x - f1.x, B1.y - f1.y);
}

// ============================== launch =====================================
extern "C" void kernel_launch(void* const* d_in, const int* in_sizes, int n_in,
                              void* d_out, int out_size)
{
    const float* feat    = (const float*)d_in[0];
    const void*  nbr     = d_in[1];
    const float* theta_w = (const float*)d_in[2];
    const float* theta_b = (const float*)d_in[3];
    const float* phi_w   = (const float*)d_in[4];
    const float* phi_b   = (const float*)d_in[5];
    float* out = (float*)d_out;

    const int n = in_sizes[0] / F_DIM;     // number of nodes
    const int K = in_sizes[1] / n;         // neighbors per node (=16)
    const int ntiles = (n + 63) / 64;

    int dev = 0;
    cudaGetDevice(&dev);
    int sms = 0;
    cudaDeviceGetAttribute(&sms, cudaDevAttrMultiProcessorCount, dev);
    int grid = sms * 4;
    if (grid > ntiles) grid = ntiles;

    gemm_mma_kernel<<<grid, 256, SM_BYTES>>>(feat, theta_w, theta_b,
                                             phi_w, phi_b, n, ntiles);

    long long pairs = ((long long)n + 1) / 2;        // 2 nodes per warp
    long long total_threads = pairs * 32;
    int g2 = (int)((total_threads + 255) / 256);
    gather_min_kernel<<<g2, 256>>>(nbr, out, n, K);
}

// round 15
// speedup vs baseline: 1.1942x; 1.0007x over previous
#include <cuda_runtime.h>
#include <cuda_fp16.h>
#include <cstdint>

// ---------------------------------------------------------------------------
// EdgeConv (mlp_layer=0, aggregate=max), restructured:
//   t      = feat @ theta_w                      [N, 64]
//   base   = t + feat @ phi_w + theta_b + phi_b  [N, 64]   (fp16 scratch)
//   out[v] = base[v] - min_k t[nbr[v,k]]         (per-feature min, fp32 out)
//
// Kernel 1: PERSISTENT single-pass fp16 mma.sync GEMM with cp.async
//           pipelining: next tile's fp32 A rows stream into smem during the
//           current tile's MMA/epilogue (hides the staging LDG latency).
// Kernel 2: standalone gather-min (2 nodes/warp), at its compulsory
//           L2-traffic floor (~24us measured across 3 rounds).
// ---------------------------------------------------------------------------

#define F_DIM 64
#define N_MAX 120000

__device__ __half g_t16[(size_t)N_MAX * F_DIM];     // fp16 t
__device__ __half g_base16[(size_t)N_MAX * F_DIM];  // fp16 base

// ============================= PTX helpers =================================
__device__ __forceinline__ uint32_t smem_u32(const void* p) {
    uint32_t a;
    asm("{ .reg .u64 tmp; cvta.to.shared.u64 tmp, %1; cvt.u32.u64 %0, tmp; }"
        : "=r"(a) : "l"(p));
    return a;
}

__device__ __forceinline__ void ldsm_x4(uint32_t* r, uint32_t addr) {
    asm volatile("ldmatrix.sync.aligned.m8n8.x4.shared.b16 {%0,%1,%2,%3}, [%4];"
                 : "=r"(r[0]), "=r"(r[1]), "=r"(r[2]), "=r"(r[3]) : "r"(addr));
}

__device__ __forceinline__ void mma16816(float* c, const uint32_t* a,
                                         const uint32_t* b) {
    asm volatile(
        "mma.sync.aligned.m16n8k16.row.col.f32.f16.f16.f32 "
        "{%0,%1,%2,%3}, {%4,%5,%6,%7}, {%8,%9}, {%0,%1,%2,%3};"
        : "+f"(c[0]), "+f"(c[1]), "+f"(c[2]), "+f"(c[3])
        : "r"(a[0]), "r"(a[1]), "r"(a[2]), "r"(a[3]), "r"(b[0]), "r"(b[1]));
}

#define CP_ASYNC_16(dst_smem, src_gmem) \
    asm volatile("cp.async.cg.shared.global [%0], [%1], 16;" \
                 :: "r"(dst_smem), "l"(src_gmem) : "memory")
#define CP_ASYNC_COMMIT() \
    asm volatile("cp.async.commit_group;" ::: "memory")
#define CP_ASYNC_WAIT0() \
    asm volatile("cp.async.wait_group 0;" ::: "memory")

// SMEM layout (dynamic, bytes):
//   A16:  64 rows x 72 fp16 (144-B rows, ldmatrix conflict-free)   9216 B
//   B16: 128 rows x 72 fp16                                       18432 B
//   F32:  64 rows x 64 fp32 staging buffer (256-B rows)           16384 B
#define SM_AH  0
#define SM_BH  9216
#define SM_F32 27648
#define SM_BYTES 44032     // < 48KB default limit -> 4 CTAs/SM

// ===================== kernel 1: persistent GEMM ===========================
__global__ __launch_bounds__(256, 4)
void gemm_mma_kernel(const float* __restrict__ feat,
                     const float* __restrict__ theta_w,
                     const float* __restrict__ theta_b,
                     const float* __restrict__ phi_w,
                     const float* __restrict__ phi_b,
                     int n, int ntiles)
{
    extern __shared__ char sm[];
    const uint32_t sbase = smem_u32(sm);
    const int tid  = threadIdx.x;
    const int wid  = tid >> 5;
    const int lane = tid & 31;

    // per-thread staging slice: 4 x 16-B chunks of the 64x64 fp32 tile
    const int s_c4  = tid & 15;            // float4 column within row
    const int s_row = tid >> 4;            // base row (0..15), +16 per p
    const uint32_t f32_dst0 = sbase + SM_F32 + s_row * 256 + s_c4 * 16;

    // ---- prologue: kick off cp.async for this CTA's first tile ------------
    {
        const int rb = blockIdx.x * 64;
#pragma unroll
        for (int p = 0; p < 4; p++) {
            int row = s_row + p * 16;
            int gr  = rb + row; if (gr >= n) gr = n - 1;   // clamp (guarded later)
            CP_ASYNC_16(f32_dst0 + p * 16 * 256,
                        &feat[(size_t)gr * F_DIM + s_c4 * 4]);
        }
        CP_ASYNC_COMMIT();
    }

    // ---- once per CTA: B -> fp16 smem [nrow][k] (overlaps the cp.async) ---
#pragma unroll
    for (int p = 0; p < 32; p++) {
        int idx = tid + p * 256;       // 0..8191
        int c   = idx & 127;           // coalesced read dim
        int k   = idx >> 7;            // 0..63
        const float* w = (c < 64) ? theta_w : phi_w;
        float v = w[k * F_DIM + (c & 63)];
        *(__half*)(sm + SM_BH + c * 144 + k * 2) = __float2half_rn(v);
    }

    const int wm = (wid & 1) * 32;
    const int wn = (wid >> 1) * 16;
    const int li = lane & 7;
    const int lg = lane >> 3;

    for (int tile = blockIdx.x; tile < ntiles; tile += gridDim.x) {
        CP_ASYNC_WAIT0();
        __syncthreads();               // F32 staged; A16 free; B ready (iter 0)

        // ---- build A16 from staged fp32 (LDS.128 -> cvt -> STS) -----------
#pragma unroll
        for (int p = 0; p < 4; p++) {
            int row = s_row + p * 16;
            float4 f = *(const float4*)(sm + SM_F32 + row * 256 + s_c4 * 16);
            __half2 h01 = __floats2half2_rn(f.x, f.y);
            __half2 h23 = __floats2half2_rn(f.z, f.w);
            *(uint2*)(sm + SM_AH + row * 144 + s_c4 * 8) =
                make_uint2(*(uint32_t*)&h01, *(uint32_t*)&h23);
        }
        __syncthreads();               // A16 visible; F32 free for next tile

        // ---- prefetch next tile's fp32 rows (overlaps MMA/epilogue) -------
        {
            int next = tile + gridDim.x;
            if (next < ntiles) {
                const int rb2 = next * 64;
#pragma unroll
                for (int p = 0; p < 4; p++) {
                    int row = s_row + p * 16;
                    int gr  = rb2 + row; if (gr >= n) gr = n - 1;
                    CP_ASYNC_16(f32_dst0 + p * 16 * 256,
                                &feat[(size_t)gr * F_DIM + s_c4 * 4]);
                }
            }
            CP_ASYNC_COMMIT();
        }

        const int rb = tile * 64;

        float accT[2][2][4], accP[2][2][4];
#pragma unroll
        for (int mt = 0; mt < 2; mt++)
#pragma unroll
            for (int nt = 0; nt < 2; nt++)
#pragma unroll
                for (int j = 0; j < 4; j++) {
                    accT[mt][nt][j] = 0.f;
                    accP[mt][nt][j] = 0.f;
                }

#pragma unroll
        for (int ks = 0; ks < 4; ks++) {
            const int k0 = ks * 16;
            uint32_t bT[2][2], bP[2][2];
            {
                int row = wn + li + (lg >> 1) * 8;
                int col = k0 + (lg & 1) * 8;
                uint32_t r[4];
                ldsm_x4(r, sbase + SM_BH + row * 144 + col * 2);
                bT[0][0] = r[0]; bT[0][1] = r[1];
                bT[1][0] = r[2]; bT[1][1] = r[3];
                ldsm_x4(r, sbase + SM_BH + (64 + row) * 144 + col * 2);
                bP[0][0] = r[0]; bP[0][1] = r[1];
                bP[1][0] = r[2]; bP[1][1] = r[3];
            }
            uint32_t a[2][4];
#pragma unroll
            for (int mt = 0; mt < 2; mt++) {
                int row = wm + mt * 16 + li + (lg & 1) * 8;
                int col = k0 + (lg >> 1) * 8;
                ldsm_x4(a[mt], sbase + SM_AH + row * 144 + col * 2);
            }
#pragma unroll
            for (int mt = 0; mt < 2; mt++)
#pragma unroll
                for (int nt = 0; nt < 2; nt++) {
                    mma16816(accT[mt][nt], a[mt], bT[nt]);
                    mma16816(accP[mt][nt], a[mt], bP[nt]);
                }
        }

        // ---- epilogue: t (fp16) and base (fp16) ---------------------------
#pragma unroll
        for (int mt = 0; mt < 2; mt++) {
            int r0 = rb + wm + mt * 16 + (lane >> 2);
#pragma unroll
            for (int nt = 0; nt < 2; nt++) {
                int col = wn + nt * 8 + 2 * (lane & 3);
                float b0 = theta_b[col]     + phi_b[col];
                float b1 = theta_b[col + 1] + phi_b[col + 1];
                if (r0 < n) {
                    size_t o = (size_t)r0 * F_DIM + col;
                    float t0 = accT[mt][nt][0], t1 = accT[mt][nt][1];
                    *(__half2*)&g_t16[o] = __floats2half2_rn(t0, t1);
                    *(__half2*)&g_base16[o] =
                        __floats2half2_rn(t0 + accP[mt][nt][0] + b0,
                                          t1 + accP[mt][nt][1] + b1);
                }
                int r1 = r0 + 8;
                if (r1 < n) {
                    size_t o = (size_t)r1 * F_DIM + col;
                    float t2 = accT[mt][nt][2], t3 = accT[mt][nt][3];
                    *(__half2*)&g_t16[o] = __floats2half2_rn(t2, t3);
                    *(__half2*)&g_base16[o] =
                        __floats2half2_rn(t2 + accP[mt][nt][2] + b0,
                                          t3 + accP[mt][nt][3] + b1);
                }
            }
        }
    }
}

// ===================== kernel 2: gather-min ================================
// TWO nodes per warp: lanes 0-15 -> node 2w, lanes 16-31 -> node 2w+1.
// Lane hl owns uint2 chunk hl of the 128-B row. Indices coalesced + shfl.
// Sole writer of out (full coverage of the poisoned buffer).
__global__ __launch_bounds__(256)
void gather_min_kernel(const void* __restrict__ nbr_raw,
                       float* __restrict__ out,
                       int n, int K)
{
    const int lane = threadIdx.x & 31;

    unsigned int probe = ((const unsigned int*)nbr_raw)[lane];
    bool oddzero = ((lane & 1) == 0) || (probe == 0u);
    const bool is64 = (__ballot_sync(0xFFFFFFFFu, oddzero) == 0xFFFFFFFFu);

    long long wpair = (blockIdx.x * (long long)blockDim.x + threadIdx.x) >> 5;
    const int half = lane >> 4;
    const int hl   = lane & 15;
    int node = (int)(wpair * 2) + half;
    if ((int)(wpair * 2) >= n) return;
    if (node >= n) node = n - 1;     // odd-tail duplicate (benign)

    int myidx;
    if (K == 16) {
        myidx = is64 ? (int)((const long long*)nbr_raw)[(size_t)node * 16 + hl]
                     : ((const int*)nbr_raw)[(size_t)node * 16 + hl];
    } else {
        myidx = 0;
    }

    const uint2* tp = (const uint2*)g_t16;   // 16 uint2 per row
    __half2 m0 = __float2half2_rn(65504.f);
    __half2 m1 = m0;

    if (K == 16) {
#pragma unroll
        for (int j = 0; j < 16; j++) {
            int uj = __shfl_sync(0xFFFFFFFFu, myidx, j, 16);
            uint2 v = __ldg(&tp[uj * 16 + hl]);
            m0 = __hmin2(m0, *(__half2*)&v.x);
            m1 = __hmin2(m1, *(__half2*)&v.y);
        }
    } else {
        for (int j = 0; j < K; j++) {
            int uj = is64 ? (int)((const long long*)nbr_raw)[(size_t)node * K + j]
                          : ((const int*)nbr_raw)[(size_t)node * K + j];
            uint2 v = __ldg(&tp[uj * 16 + hl]);
            m0 = __hmin2(m0, *(__half2*)&v.x);
            m1 = __hmin2(m1, *(__half2*)&v.y);
        }
    }

    size_t o = (size_t)node * 16 + hl;
    uint2 bb = *((const uint2*)g_base16 + o);
    float2 B0 = __half22float2(*(__half2*)&bb.x);
    float2 B1 = __half22float2(*(__half2*)&bb.y);
    float2 f0 = __half22float2(m0);
    float2 f1 = __half22float2(m1);
    ((float4*)out)[o] = make_float4(B0.x - f0.x, B0.y - f0.y,
                                    B1.x - f1.x, B1.y - f1.y);
}

// ============================== launch =====================================
extern "C" void kernel_launch(void* const* d_in, const int* in_sizes, int n_in,
                              void* d_out, int out_size)
{
    const float* feat    = (const float*)d_in[0];
    const void*  nbr     = d_in[1];
    const float* theta_w = (const float*)d_in[2];
    const float* theta_b = (const float*)d_in[3];
    const float* phi_w   = (const float*)d_in[4];
    const float* phi_b   = (const float*)d_in[5];
    float* out = (float*)d_out;

    const int n = in_sizes[0] / F_DIM;     // number of nodes
    const int K = in_sizes[1] / n;         // neighbors per node (=16)
    const int ntiles = (n + 63) / 64;

    int dev = 0;
    cudaGetDevice(&dev);
    int sms = 0;
    cudaDeviceGetAttribute(&sms, cudaDevAttrMultiProcessorCount, dev);
    int grid = sms * 4;
    if (grid > ntiles) grid = ntiles;

    gemm_mma_kernel<<<grid, 256, SM_BYTES>>>(feat, theta_w, theta_b,
                                             phi_w, phi_b, n, ntiles);

    long long pairs = ((long long)n + 1) / 2;        // 2 nodes per warp
    long long total_threads = pairs * 32;
    int g2 = (int)((total_threads + 255) / 256);
    gather_min_kernel<<<g2, 256>>>(nbr, out, n, K);
}